// round 11
// baseline (speedup 1.0000x reference)
#include <cuda_runtime.h>
#include <cstdint>

// ---------------------------------------------------------------------------
// f = -d( sum(mlp(pos)) )/dpos for a 2->8->4->2 ReLU MLP.
//
// Force is piecewise constant in the ReLU masks (m1: 8 bits, m2: 4 bits):
//   force(m1,m2) = -sum_{k: m1_k active} v[m2][k] * W1[k,:]
//   v[m2][k]     =  sum_{j: m2_j active} g3_j * W2[j][k],  g3_j = W3[0][j]+W3[1][j]
// Merged 4096-entry smem table  tab[(m2<<8)|m1] -> float2 (negation folded).
// Forward packed 2-neurons-per-lane with fma.rn.f32x2.
// Round 8: 4 float4 per thread (8 positions), loads front-batched -> enough
// ILP to hide DRAM + LDS latency at 2 CTAs/SM (latency-bound fix).
// ---------------------------------------------------------------------------

typedef unsigned long long u64;

__device__ __forceinline__ unsigned prmt_(unsigned a, unsigned b, unsigned sel) {
    unsigned d;
    asm("prmt.b32 %0, %1, %2, %3;" : "=r"(d) : "r"(a), "r"(b), "r"(sel));
    return d;
}
__device__ __forceinline__ int dp4a_(unsigned a, unsigned b, int c) {
    int d;
    asm("dp4a.u32.u32 %0, %1, %2, %3;" : "=r"(d) : "r"(a), "r"(b), "r"(c));
    return d;
}
__device__ __forceinline__ u64 pack2_(float lo, float hi) {
    u64 r;
    asm("mov.b64 %0, {%1, %2};" : "=l"(r) : "f"(lo), "f"(hi));
    return r;
}
__device__ __forceinline__ void unpack2_(u64 v, float& lo, float& hi) {
    asm("mov.b64 {%0, %1}, %2;" : "=f"(lo), "=f"(hi) : "l"(v));
}
__device__ __forceinline__ u64 fma2_(u64 a, u64 b, u64 c) {
    u64 d;
    asm("fma.rn.f32x2 %0, %1, %2, %3;" : "=l"(d) : "l"(a), "l"(b), "l"(c));
    return d;
}
__device__ __forceinline__ u64 mul2_(u64 a, u64 b) {
    u64 d;
    asm("mul.rn.f32x2 %0, %1, %2;" : "=l"(d) : "l"(a), "l"(b));
    return d;
}

struct Wts {
    u64 w1x2[4], w1y2[4], b12[4];   // neuron pairs (2i, 2i+1)
    u64 w2p[4][4];                   // W2[j][2i..2i+1] packed
    float b2[4];
};

__device__ __forceinline__ float2 force_one(float x, float y, const Wts& W,
                                            const float2* __restrict__ tab) {
    u64 xx = pack2_(x, x), yy = pack2_(y, y);

    // ---- layer 1 pre-activations, 2 neurons per FFMA2 ----
    u64 h1p2[4];
#pragma unroll
    for (int i = 0; i < 4; i++)
        h1p2[i] = fma2_(xx, W.w1x2[i], fma2_(yy, W.w1y2[i], W.b12[i]));

    float h1p[8];
#pragma unroll
    for (int i = 0; i < 4; i++) unpack2_(h1p2[i], h1p[2 * i], h1p[2 * i + 1]);

    // ---- m1: bit k = 1 iff h1p[k] < 0 (inactive) ----
    unsigned a01 = prmt_(__float_as_uint(h1p[0]), __float_as_uint(h1p[1]), 0x00FBu);
    unsigned a23 = prmt_(__float_as_uint(h1p[2]), __float_as_uint(h1p[3]), 0x00FBu);
    unsigned a45 = prmt_(__float_as_uint(h1p[4]), __float_as_uint(h1p[5]), 0x00FBu);
    unsigned a67 = prmt_(__float_as_uint(h1p[6]), __float_as_uint(h1p[7]), 0x00FBu);
    unsigned tLo = prmt_(a01, a23, 0x5410u) & 0x01010101u;
    unsigned tHi = prmt_(a45, a67, 0x5410u) & 0x01010101u;
    int m1 = dp4a_(tHi, 0x80402010u, dp4a_(tLo, 0x08040201u, 0));   // 0..255

    // ---- relu + repack ----
    u64 h1_2[4];
#pragma unroll
    for (int i = 0; i < 4; i++)
        h1_2[i] = pack2_(fmaxf(h1p[2 * i], 0.0f), fmaxf(h1p[2 * i + 1], 0.0f));

    // ---- layer 2 pre-activations (signs only) ----
    float h2p[4];
#pragma unroll
    for (int j = 0; j < 4; j++) {
        u64 acc = mul2_(h1_2[0], W.w2p[j][0]);
        acc = fma2_(h1_2[1], W.w2p[j][1], acc);
        acc = fma2_(h1_2[2], W.w2p[j][2], acc);
        acc = fma2_(h1_2[3], W.w2p[j][3], acc);
        float l, h;
        unpack2_(acc, l, h);
        h2p[j] = (l + h) + W.b2[j];
    }

    // ---- m2: bit j = 1 iff h2p[j] < 0 (inactive) ----
    unsigned b01 = prmt_(__float_as_uint(h2p[0]), __float_as_uint(h2p[1]), 0x00FBu);
    unsigned b23 = prmt_(__float_as_uint(h2p[2]), __float_as_uint(h2p[3]), 0x00FBu);
    unsigned bm  = prmt_(b01, b23, 0x5410u) & 0x01010101u;
    int m2 = dp4a_(bm, 0x08040201u, 0);                              // 0..15

    return tab[(m2 << 8) | m1];   // negation folded into the table
}

#define ILP 4

__global__ __launch_bounds__(256, 2)
void toy_force_kernel(const float4* __restrict__ pos4,
                      const float* __restrict__ W1,
                      const float* __restrict__ b1,
                      const float* __restrict__ W2,
                      const float* __restrict__ b2,
                      const float* __restrict__ W3,
                      float4* __restrict__ out4,
                      int n4) {
    __shared__ float2 tab[4096];   // [(m2<<8) | m1] -> -force

    int t = threadIdx.x;

    // ---- front-batched loads: ILP x LDG.128 in flight (MLP_p1 = ILP) ----
    int base = blockIdx.x * (256 * ILP) + t;
    bool full = (blockIdx.x * (256 * ILP) + 256 * ILP) <= n4;  // uniform branch

    float4 p[ILP];
#pragma unroll
    for (int i = 0; i < ILP; i++) p[i] = make_float4(0.f, 0.f, 0.f, 0.f);

    if (full) {
#pragma unroll
        for (int i = 0; i < ILP; i++) p[i] = __ldg(&pos4[base + i * 256]);
    } else {
#pragma unroll
        for (int i = 0; i < ILP; i++)
            if (base + i * 256 < n4) p[i] = __ldg(&pos4[base + i * 256]);
    }

    // ---- build the merged force table (overlaps LDG latency) ----
    {
        float g3[4];
#pragma unroll
        for (int j = 0; j < 4; j++) g3[j] = W3[j] + W3[4 + j];  // W3 [2,4] row-major

        int m2  = t >> 4;
        int lo4 = t & 15;

        float v[8];
#pragma unroll
        for (int k = 0; k < 8; k++) {
            float s = 0.f;
#pragma unroll
            for (int j = 0; j < 4; j++)
                if (!((m2 >> j) & 1)) s = fmaf(g3[j], W2[j * 8 + k], s);
            v[k] = s;
        }

        float lx = 0.f, ly = 0.f;          // neurons 0..3 (fixed per thread)
#pragma unroll
        for (int k = 0; k < 4; k++) {
            if (!((lo4 >> k) & 1)) {
                lx = fmaf(v[k], W1[2 * k + 0], lx);
                ly = fmaf(v[k], W1[2 * k + 1], ly);
            }
        }

        int ebase = (m2 << 8) | lo4;
#pragma unroll
        for (int hi = 0; hi < 16; hi++) {
            float fx = lx, fy = ly;
#pragma unroll
            for (int k = 0; k < 4; k++) {
                if (!((hi >> k) & 1)) {
                    fx = fmaf(v[k + 4], W1[2 * (k + 4) + 0], fx);
                    fy = fmaf(v[k + 4], W1[2 * (k + 4) + 1], fy);
                }
            }
            tab[ebase | (hi << 4)] = make_float2(-fx, -fy);
        }
    }

    // ---- packed weights in registers ----
    Wts W;
#pragma unroll
    for (int i = 0; i < 4; i++) {
        W.w1x2[i] = pack2_(W1[4 * i + 0], W1[4 * i + 2]);
        W.w1y2[i] = pack2_(W1[4 * i + 1], W1[4 * i + 3]);
        W.b12[i]  = pack2_(b1[2 * i], b1[2 * i + 1]);
    }
#pragma unroll
    for (int j = 0; j < 4; j++) {
        W.b2[j] = b2[j];
#pragma unroll
        for (int i = 0; i < 4; i++)
            W.w2p[j][i] = pack2_(W2[j * 8 + 2 * i], W2[j * 8 + 2 * i + 1]);
    }
    __syncthreads();

    // ---- compute 2*ILP independent positions, then store ----
    if (full) {
#pragma unroll
        for (int i = 0; i < ILP; i++) {
            float2 f0 = force_one(p[i].x, p[i].y, W, tab);
            float2 f1 = force_one(p[i].z, p[i].w, W, tab);
            out4[base + i * 256] = make_float4(f0.x, f0.y, f1.x, f1.y);
        }
    } else {
#pragma unroll
        for (int i = 0; i < ILP; i++) {
            if (base + i * 256 < n4) {
                float2 f0 = force_one(p[i].x, p[i].y, W, tab);
                float2 f1 = force_one(p[i].z, p[i].w, W, tab);
                out4[base + i * 256] = make_float4(f0.x, f0.y, f1.x, f1.y);
            }
        }
    }
}

extern "C" void kernel_launch(void* const* d_in, const int* in_sizes, int n_in,
                              void* d_out, int out_size) {
    const float* pos = (const float*)d_in[0];   // [N,2] float32
    const float* W1  = (const float*)d_in[1];   // [8,2]
    const float* b1  = (const float*)d_in[2];   // [8]
    const float* W2  = (const float*)d_in[3];   // [4,8]
    const float* b2  = (const float*)d_in[4];   // [4]
    const float* W3  = (const float*)d_in[5];   // [2,4]
    float* out = (float*)d_out;                 // [N,2] float32

    int n4 = in_sizes[0] / 4;                   // float4s (2 positions each)
    const int threads = 256;
    const int per_block = threads * ILP;        // ILP float4 per thread
    int blocks = (n4 + per_block - 1) / per_block;

    toy_force_kernel<<<blocks, threads>>>(
        (const float4*)pos, W1, b1, W2, b2, W3, (float4*)out, n4);
}